// round 16
// baseline (speedup 1.0000x reference)
#include <cuda_runtime.h>
#include <cstdint>

// Spatial correlation sampler:
// out[b, di*9+dj, i, j] = (1/C) * sum_c x[b,c,i,j] * y[b,c,i+di-4, j+dj-4]  (zero-padded)
// x,y = [16, 256, 64, 64] fp32; out = [16, 81, 64, 64] fp32.

#define BB 16
#define CH 256
#define HH 64
#define WW 64
#define TH 8            // output rows per CTA
#define CC 2            // channels per smem stage (fine-grained)
#define NS (CH / CC)    // 128 stages
#define DI_CHUNK 3
#define YR (TH + 2)     // 10 y rows per stage
#define YW 72           // 64 + 2*4 pad
#define XF4 (CC * TH * WW / 4)   // 256 float4 per x stage
#define YF4 (CC * YR * 18)       // 360 float4 per y stage
#define CHSTR (HH * WW)          // channel stride (floats)
#define STAGESTR (CC * CHSTR)    // gmem advance per stage (floats)
#define NBUF 4                   // ring depth (3 cp.async groups in flight)

#define FMA2(acc, a, b) \
    asm("fma.rn.f32x2 %0, %1, %2, %0;" : "+l"(acc) : "l"(a), "l"(b))
#define PACK2(r, lo, hi) \
    asm("mov.b64 %0, {%1, %2};" : "=l"(r) : "r"(__float_as_uint(lo)), "r"(__float_as_uint(hi)))
#define UNPK2(lo, hi, r) \
    asm("mov.b64 {%0, %1}, %2;" : "=f"(lo), "=f"(hi) : "l"(r))

__device__ __forceinline__ void cpa16(uint32_t saddr, const void* gptr, int src_bytes) {
    asm volatile("cp.async.cg.shared.global [%0], [%1], 16, %2;\n"
                 :: "r"(saddr), "l"(gptr), "r"(src_bytes));
}

__global__ __launch_bounds__(128, 3)
void corr_kernel(const float* __restrict__ x,
                 const float* __restrict__ y,
                 float* __restrict__ out)
{
    __shared__ float xs[NBUF][CC][TH][WW];   // 4 * 4 KB    = 16 KB
    __shared__ float ys[NBUF][CC][YR][YW];   // 4 * 5.76 KB = 23.04 KB  => 39 KB

    const int tid = threadIdx.x;       // 128 threads
    const int jg  = tid & 15;
    const int ti  = tid >> 4;
    const int j0  = jg * 4;            // 4 pixels per thread
    const int i0  = blockIdx.x * TH;
    const int g   = blockIdx.y * DI_CHUNK;
    const int b   = blockIdx.z;        // batch slowest -> L2 locality across passes

    const float* xb = x + (size_t)b * CH * CHSTR;
    const float* yb = y + (size_t)b * CH * CHSTR;

    const uint32_t xs_s  = (uint32_t)__cvta_generic_to_shared(&xs[0][0][0][0]);
    const uint32_t ys_s  = (uint32_t)__cvta_generic_to_shared(&ys[0][0][0][0]);
    const uint32_t xs_sz = sizeof(float) * CC * TH * WW;
    const uint32_t ys_sz = sizeof(float) * CC * YR * YW;

    // ---- hoisted loader addresses
    // x: 256 float4/stage -> 2 per thread
    const float* gx[2];  uint32_t sx[2];
#pragma unroll
    for (int e = 0; e < 2; e++) {
        int f   = tid + e * 128;
        int c   = f >> 7;             // / (TH*WW/4 = 128)
        int rem = f & 127;
        int r   = rem >> 4;
        int q4  = rem & 15;
        gx[e] = xb + c * CHSTR + (i0 + r) * WW + q4 * 4;
        sx[e] = xs_s + (uint32_t)f * 16u;
    }
    // y: 360 float4/stage -> up to 3 per thread, zero-padded edges
    const float* gyp[3]; uint32_t sy[3]; int ybytes[3]; bool yvalid[3];
#pragma unroll
    for (int e = 0; e < 3; e++) {
        int f = tid + e * 128;
        yvalid[e] = (f < YF4);
        int fc = yvalid[e] ? f : 0;
        int c   = fc / (YR * 18);
        int rem = fc % (YR * 18);
        int r   = rem / 18;
        int q   = rem % 18;
        int gy  = i0 + g - 4 + r;
        bool ok = (gy >= 0) && (gy < HH) && (q > 0) && (q < 17);
        int gyc = gy < 0 ? 0 : (gy > HH - 1 ? HH - 1 : gy);
        int gq  = ok ? (q * 4 - 4) : 0;
        gyp[e]    = yb + c * CHSTR + gyc * WW + gq;
        sy[e]     = ys_s + (uint32_t)(((c * YR + r) * YW) + q * 4) * 4u;
        ybytes[e] = ok ? 16 : 0;
    }

    // f32x2 accumulators
    unsigned long long acc2[DI_CHUNK][9][2];
#pragma unroll
    for (int a = 0; a < DI_CHUNK; a++)
#pragma unroll
        for (int d = 0; d < 9; d++) { acc2[a][d][0] = 0ull; acc2[a][d][1] = 0ull; }

    // ---- issue one stage's cp.asyncs (call strictly sequentially: advances ptrs)
    auto issue_stage = [&](int sel) {
        uint32_t xo = (uint32_t)sel * xs_sz;
        uint32_t yo = (uint32_t)sel * ys_sz;
#pragma unroll
        for (int e = 0; e < 2; e++) {
            cpa16(sx[e] + xo, gx[e], 16);
            gx[e] += STAGESTR;
        }
#pragma unroll
        for (int e = 0; e < 3; e++) {
            if (yvalid[e]) {
                cpa16(sy[e] + yo, gyp[e], ybytes[e]);
                gyp[e] += STAGESTR;
            }
        }
        asm volatile("cp.async.commit_group;\n");
    };

    issue_stage(0);
    issue_stage(1);
    issue_stage(2);

    for (int t = 0; t < NS; t++) {
        const int sel = t & (NBUF - 1);
        // group t must be complete; keep later groups in flight
        if (t < NS - 2)      asm volatile("cp.async.wait_group 2;\n");
        else if (t == NS - 2) asm volatile("cp.async.wait_group 1;\n");
        else                  asm volatile("cp.async.wait_group 0;\n");
        __syncthreads();                              // single barrier per stage
        if (t + 3 < NS) issue_stage((t + 3) & (NBUF - 1));

        // ---- compute on buffer `sel`
#pragma unroll
        for (int c = 0; c < CC; c++) {
            float4 xv = *(const float4*)&xs[sel][c][ti][j0];
            unsigned long long xlo, xhi;
            PACK2(xlo, xv.x, xv.y);
            PACK2(xhi, xv.z, xv.w);
#pragma unroll
            for (int a = 0; a < DI_CHUNK; a++) {
                float4 t0 = *(const float4*)&ys[sel][c][ti + a][j0 + 0];
                float4 t1 = *(const float4*)&ys[sel][c][ti + a][j0 + 4];
                float4 t2 = *(const float4*)&ys[sel][c][ti + a][j0 + 8];
                float wv[12] = { t0.x, t0.y, t0.z, t0.w,
                                 t1.x, t1.y, t1.z, t1.w,
                                 t2.x, t2.y, t2.z, t2.w };
                unsigned long long wp[11];
#pragma unroll
                for (int k = 0; k < 11; k++) PACK2(wp[k], wv[k], wv[k + 1]);
#pragma unroll
                for (int d = 0; d < 9; d++) {
                    FMA2(acc2[a][d][0], xlo, wp[d]);
                    FMA2(acc2[a][d][1], xhi, wp[d + 2]);
                }
            }
        }
        // no trailing barrier: next iteration's top barrier protects buffer reuse
    }

    // ---- epilogue: scale by 1/C, coalesced float4 stores
    const float s = 1.0f / (float)CH;
#pragma unroll
    for (int a = 0; a < DI_CHUNK; a++) {
#pragma unroll
        for (int d = 0; d < 9; d++) {
            int dd = (g + a) * 9 + d;
            float v0, v1, v2, v3;
            UNPK2(v0, v1, acc2[a][d][0]);
            UNPK2(v2, v3, acc2[a][d][1]);
            float4 v = make_float4(v0 * s, v1 * s, v2 * s, v3 * s);
            *(float4*)&out[(((size_t)b * 81 + dd) * HH + (i0 + ti)) * WW + j0] = v;
        }
    }
}

extern "C" void kernel_launch(void* const* d_in, const int* in_sizes, int n_in,
                              void* d_out, int out_size)
{
    const float* x = (const float*)d_in[0];
    const float* y = (const float*)d_in[1];
    float* out = (float*)d_out;

    dim3 grid(HH / TH, 9 / DI_CHUNK, BB);   // (8, 3, 16) = 384 CTAs, single wave @ 3 CTA/SM
    dim3 block(128);
    corr_kernel<<<grid, block>>>(x, y, out);
}

// round 17
// speedup vs baseline: 1.1680x; 1.1680x over previous
#include <cuda_runtime.h>
#include <cstdint>

// Spatial correlation sampler:
// out[b, di*9+dj, i, j] = (1/C) * sum_c x[b,c,i,j] * y[b,c,i+di-4, j+dj-4]  (zero-padded)
// x,y = [16, 256, 64, 64] fp32; out = [16, 81, 64, 64] fp32.

#define BB 16
#define CH 256
#define HH 64
#define WW 64
#define TH 8            // output rows per CTA
#define CC 4            // channels per smem stage
#define NS (CH / CC)    // 64 stages
#define DI_CHUNK 3
#define YR (TH + 2)     // 10 y rows per stage
#define YW 72           // 64 + 2*4 pad
#define XF4 (CC * TH * WW / 4)   // 512 float4 per x stage
#define YF4 (CC * YR * 18)       // 720 float4 per y stage
#define CHSTR (HH * WW)          // channel stride (floats)
#define STAGESTR (CC * CHSTR)    // gmem advance per stage (floats)

typedef unsigned long long u64;

#define FMA2(acc, a, b) \
    asm("fma.rn.f32x2 %0, %1, %2, %0;" : "+l"(acc) : "l"(a), "l"(b))
// pack two u32 register halves into an f32x2 operand (hi-half extract is a free reg-select)
#define PACK2U(r, lo, hi) \
    asm("mov.b64 %0, {%1, %2};" : "=l"(r) : "r"(lo), "r"(hi))
#define UNPK2(lo, hi, r) \
    asm("mov.b64 {%0, %1}, %2;" : "=f"(lo), "=f"(hi) : "l"(r))

#define LO32(u) ((uint32_t)(u))
#define HI32(u) ((uint32_t)((u) >> 32))

__device__ __forceinline__ void cpa16(uint32_t saddr, const void* gptr, int src_bytes) {
    asm volatile("cp.async.cg.shared.global [%0], [%1], 16, %2;\n"
                 :: "r"(saddr), "l"(gptr), "r"(src_bytes));
}

__global__ __launch_bounds__(128, 2)
void corr_kernel(const float* __restrict__ x,
                 const float* __restrict__ y,
                 float* __restrict__ out)
{
    __shared__ float xs[2][CC][TH][WW];   // 2 * 8 KB
    __shared__ float ys[2][CC][YR][YW];   // 2 * 11.25 KB  => 38.5 KB total

    const int tid = threadIdx.x;       // 128 threads
    const int jg  = tid & 15;
    const int ti  = tid >> 4;
    const int j0  = jg * 4;            // 4 pixels per thread
    const int i0  = blockIdx.x * TH;
    const int g   = blockIdx.y * DI_CHUNK;
    const int b   = blockIdx.z;        // batch slowest -> L2 locality across passes

    const float* xb = x + (size_t)b * CH * CHSTR;
    const float* yb = y + (size_t)b * CH * CHSTR;

    const uint32_t xs_s  = (uint32_t)__cvta_generic_to_shared(&xs[0][0][0][0]);
    const uint32_t ys_s  = (uint32_t)__cvta_generic_to_shared(&ys[0][0][0][0]);
    const uint32_t xs_sz = sizeof(float) * CC * TH * WW;
    const uint32_t ys_sz = sizeof(float) * CC * YR * YW;

    // ---- hoisted loader addresses
    // x: 512 float4/stage -> 4 per thread
    const float* gx[4];  uint32_t sx[4];
#pragma unroll
    for (int e = 0; e < 4; e++) {
        int f   = tid + e * 128;
        int c   = f >> 7;             // / (TH*WW/4 = 128)
        int rem = f & 127;
        int r   = rem >> 4;
        int q4  = rem & 15;
        gx[e] = xb + c * CHSTR + (i0 + r) * WW + q4 * 4;
        sx[e] = xs_s + (uint32_t)f * 16u;
    }
    // y: 720 float4/stage -> up to 6 per thread, zero-padded edges
    const float* gyp[6]; uint32_t sy[6]; int ybytes[6]; bool yvalid[6];
#pragma unroll
    for (int e = 0; e < 6; e++) {
        int f = tid + e * 128;
        yvalid[e] = (f < YF4);
        int fc = yvalid[e] ? f : 0;
        int c   = fc / (YR * 18);
        int rem = fc % (YR * 18);
        int r   = rem / 18;
        int q   = rem % 18;
        int gy  = i0 + g - 4 + r;
        bool ok = (gy >= 0) && (gy < HH) && (q > 0) && (q < 17);
        int gyc = gy < 0 ? 0 : (gy > HH - 1 ? HH - 1 : gy);
        int gq  = ok ? (q * 4 - 4) : 0;
        gyp[e]    = yb + c * CHSTR + gyc * WW + gq;
        sy[e]     = ys_s + (uint32_t)(((c * YR + r) * YW) + q * 4) * 4u;
        ybytes[e] = ok ? 16 : 0;
    }

    // f32x2 accumulators
    u64 acc2[DI_CHUNK][9][2];
#pragma unroll
    for (int a = 0; a < DI_CHUNK; a++)
#pragma unroll
        for (int d = 0; d < 9; d++) { acc2[a][d][0] = 0ull; acc2[a][d][1] = 0ull; }

    // ---- issue one stage's cp.asyncs (call strictly sequentially: advances ptrs)
    auto issue_stage = [&](int sel) {
        uint32_t xo = sel ? xs_sz : 0u;
        uint32_t yo = sel ? ys_sz : 0u;
#pragma unroll
        for (int e = 0; e < 4; e++) {
            cpa16(sx[e] + xo, gx[e], 16);
            gx[e] += STAGESTR;
        }
#pragma unroll
        for (int e = 0; e < 6; e++) {
            if (yvalid[e]) {
                cpa16(sy[e] + yo, gyp[e], ybytes[e]);
                gyp[e] += STAGESTR;
            }
        }
        asm volatile("cp.async.commit_group;\n");
    };

    issue_stage(0);

    for (int t = 0; t < NS; t++) {
        const int sel = t & 1;
        asm volatile("cp.async.wait_group 0;\n");
        __syncthreads();                       // single barrier per stage
        if (t + 1 < NS) issue_stage(sel ^ 1);  // overlaps with compute below

        // ---- compute on buffer `sel` (even/odd f32x2 packing)
#pragma unroll
        for (int c = 0; c < CC; c++) {
            // x pairs arrive as aligned register pairs: zero pack cost
            ulonglong2 xu = *(const ulonglong2*)&xs[sel][c][ti][j0];
            const u64 xlo = xu.x, xhi = xu.y;
#pragma unroll
            for (int a = 0; a < DI_CHUNK; a++) {
                ulonglong2 u0 = *(const ulonglong2*)&ys[sel][c][ti + a][j0 + 0];
                ulonglong2 u1 = *(const ulonglong2*)&ys[sel][c][ti + a][j0 + 4];
                ulonglong2 u2 = *(const ulonglong2*)&ys[sel][c][ti + a][j0 + 8];
                // even pairs (free): p0..p5 = (w0,w1)(w2,w3)(w4,w5)(w6,w7)(w8,w9)(w10,w11)
                const u64 p0 = u0.x, p1 = u0.y, p2 = u1.x,
                          p3 = u1.y, p4 = u2.x, p5 = u2.y;
                // odd pairs (5 packs from register halves)
                u64 q0, q1, q2, q3, q4;
                PACK2U(q0, HI32(u0.x), LO32(u0.y));   // (w1,w2)
                PACK2U(q1, HI32(u0.y), LO32(u1.x));   // (w3,w4)
                PACK2U(q2, HI32(u1.x), LO32(u1.y));   // (w5,w6)
                PACK2U(q3, HI32(u1.y), LO32(u2.x));   // (w7,w8)
                PACK2U(q4, HI32(u2.x), LO32(u2.y));   // (w9,w10)

                // d even: lo uses p[d/2], hi uses p[d/2+1]
                // d odd : lo uses q[(d-1)/2], hi uses q[(d+1)/2]
                FMA2(acc2[a][0][0], xlo, p0);  FMA2(acc2[a][0][1], xhi, p1);
                FMA2(acc2[a][1][0], xlo, q0);  FMA2(acc2[a][1][1], xhi, q1);
                FMA2(acc2[a][2][0], xlo, p1);  FMA2(acc2[a][2][1], xhi, p2);
                FMA2(acc2[a][3][0], xlo, q1);  FMA2(acc2[a][3][1], xhi, q2);
                FMA2(acc2[a][4][0], xlo, p2);  FMA2(acc2[a][4][1], xhi, p3);
                FMA2(acc2[a][5][0], xlo, q2);  FMA2(acc2[a][5][1], xhi, q3);
                FMA2(acc2[a][6][0], xlo, p3);  FMA2(acc2[a][6][1], xhi, p4);
                FMA2(acc2[a][7][0], xlo, q3);  FMA2(acc2[a][7][1], xhi, q4);
                FMA2(acc2[a][8][0], xlo, p4);  FMA2(acc2[a][8][1], xhi, p5);
            }
        }
        // no trailing barrier: next iteration's top barrier protects buffer reuse
    }

    // ---- epilogue: scale by 1/C, coalesced float4 stores
    const float s = 1.0f / (float)CH;
#pragma unroll
    for (int a = 0; a < DI_CHUNK; a++) {
#pragma unroll
        for (int d = 0; d < 9; d++) {
            int dd = (g + a) * 9 + d;
            float v0, v1, v2, v3;
            UNPK2(v0, v1, acc2[a][d][0]);
            UNPK2(v2, v3, acc2[a][d][1]);
            float4 v = make_float4(v0 * s, v1 * s, v2 * s, v3 * s);
            *(float4*)&out[(((size_t)b * 81 + dd) * HH + (i0 + ti)) * WW + j0] = v;
        }
    }
}

extern "C" void kernel_launch(void* const* d_in, const int* in_sizes, int n_in,
                              void* d_out, int out_size)
{
    const float* x = (const float*)d_in[0];
    const float* y = (const float*)d_in[1];
    float* out = (float*)d_out;

    dim3 grid(HH / TH, 9 / DI_CHUNK, BB);   // (8, 3, 16) = 384 CTAs
    dim3 block(128);
    corr_kernel<<<grid, block>>>(x, y, out);
}